// round 17
// baseline (speedup 1.0000x reference)
#include <cuda_runtime.h>
#include <cuda_bf16.h>
#include <cuda_fp16.h>
#include <cstdint>

#define NWIN   2048
#define WIN    64
#define DIM    256
#define HEADS  8
#define HD     32
#define QKV_N  768
#define MROWS  (NWIN*WIN)  // 131072

__device__ __half g_qh[(size_t)NWIN*HEADS*WIN*HD];
__device__ __half g_kh[(size_t)NWIN*HEADS*WIN*HD];
__device__ __half g_vh[(size_t)NWIN*HEADS*WIN*HD];
__device__ __half g_bmh[(size_t)256*HEADS*WIN*WIN];
__device__ __half g_xh[(size_t)MROWS*DIM];
__device__ __half g_aoh[(size_t)MROWS*DIM];
__device__ __half g_wqh[QKV_N*DIM];
__device__ __half g_wph[DIM*DIM];

__device__ __forceinline__ uint32_t pack_f16(float a, float b) {
    __half2 t = __floats2half2_rn(a, b);
    return *(uint32_t*)&t;
}

__device__ __forceinline__ void mma_f16(float c[4],
                                        unsigned a0, unsigned a1, unsigned a2, unsigned a3,
                                        unsigned b0, unsigned b1) {
    asm volatile(
        "mma.sync.aligned.m16n8k16.row.col.f32.f16.f16.f32 "
        "{%0,%1,%2,%3}, {%4,%5,%6,%7}, {%8,%9}, {%0,%1,%2,%3};"
        : "+f"(c[0]), "+f"(c[1]), "+f"(c[2]), "+f"(c[3])
        : "r"(a0), "r"(a1), "r"(a2), "r"(a3), "r"(b0), "r"(b1));
}

__device__ __forceinline__ void ldsm_x4(unsigned& r0, unsigned& r1, unsigned& r2,
                                        unsigned& r3, uint32_t addr) {
    asm volatile("ldmatrix.sync.aligned.m8n8.x4.shared.b16 {%0,%1,%2,%3}, [%4];"
                 : "=r"(r0), "=r"(r1), "=r"(r2), "=r"(r3) : "r"(addr));
}

__device__ __forceinline__ void cp16(uint32_t dst, const void* src) {
    asm volatile("cp.async.cg.shared.global [%0], [%1], 16;" :: "r"(dst), "l"(src));
}

// ---------------------------------------------------------------------------
// fp32 -> fp16 conversion pre-pass
// ---------------------------------------------------------------------------
__global__ void conv_f16(const float* __restrict__ src, __half* __restrict__ dst, int n4)
{
    const int i = blockIdx.x * 256 + threadIdx.x;
    if (i < n4) {
        float4 v = ((const float4*)src)[i];
        ((uint2*)dst)[i] = make_uint2(pack_f16(v.x, v.y), pack_f16(v.z, v.w));
    }
}

// ---------------------------------------------------------------------------
// bias+mask tables (fp16), 4 elements per thread
// ---------------------------------------------------------------------------
__global__ void bm_pre(const float* __restrict__ bt, const int* __restrict__ rpi,
                       const float* __restrict__ mask)
{
    const int i4 = blockIdx.x * 256 + threadIdx.x;
    const int e = (i4 & 1023) * 4;
    const int h = (i4 >> 10) & 7;
    const int w = i4 >> 13;
    float4 m = *(const float4*)&mask[w * 4096 + e];
    const float b0 = bt[rpi[e]     * HEADS + h];
    const float b1 = bt[rpi[e + 1] * HEADS + h];
    const float b2 = bt[rpi[e + 2] * HEADS + h];
    const float b3 = bt[rpi[e + 3] * HEADS + h];
    *(uint2*)&g_bmh[(((size_t)(w * 8 + h)) << 12) + e] =
        make_uint2(pack_f16(b0 + m.x, b1 + m.y), pack_f16(b2 + m.z, b3 + m.w));
}

// ---------------------------------------------------------------------------
// GEMM: fp16 cp.async 2-stage, block 128x128, warp 64x64, LDSM fragments.
// ---------------------------------------------------------------------------
#define GP 40

template<bool QKV>
__global__ void __launch_bounds__(128, 2) mma_gemm(const __half* __restrict__ A,
                                                   const __half* __restrict__ W,
                                                   const float* __restrict__ bias,
                                                   float* __restrict__ out)
{
    const int K = DIM;
    __shared__ __half As[2][128 * GP];
    __shared__ __half Bs[2][128 * GP];
    uint32_t sA[2], sB[2];
    #pragma unroll
    for (int s = 0; s < 2; s++) {
        sA[s] = (uint32_t)__cvta_generic_to_shared(&As[s][0]);
        sB[s] = (uint32_t)__cvta_generic_to_shared(&Bs[s][0]);
    }

    const int rowBase = blockIdx.y * 128;
    const int colBase = blockIdx.x * 128;
    const int tid  = threadIdx.x;
    const int lane = tid & 31;
    const int warp = tid >> 5;
    const int warpM = warp >> 1;
    const int warpN = warp & 1;
    const int g  = lane >> 2;
    const int tg = lane & 3;
    const int m0 = warpM * 64;
    const int n0 = warpN * 64;

    // ldmatrix lane addressing: row = base + (lane&15), col = k0 + (lane>>4)*8
    const int lrow = lane & 15;
    const int lcol = (lane >> 4) << 3;

    const int lr = tid >> 2;
    const int lc8 = (tid & 3) * 8;

    auto issue = [&](int buf, int kb) {
        #pragma unroll
        for (int i = 0; i < 4; i++) {
            const int r = lr + 32 * i;
            const uint32_t off = (uint32_t)(r * GP + lc8) * 2;
            cp16(sA[buf] + off, &A[(size_t)(rowBase + r) * K + kb + lc8]);
            cp16(sB[buf] + off, &W[(size_t)(colBase + r) * K + kb + lc8]);
        }
        asm volatile("cp.async.commit_group;");
    };

    issue(0, 0);
    issue(1, 32);

    float acc[4][8][4] = {};

    for (int it = 0; it < 8; it++) {
        if (it == 7) asm volatile("cp.async.wait_group 0;");
        else         asm volatile("cp.async.wait_group 1;");
        __syncthreads();
        const uint32_t as = sA[it & 1];
        const uint32_t bs = sB[it & 1];

        #pragma unroll
        for (int ks = 0; ks < 2; ks++) {
            const int k0 = ks * 16;
            unsigned a[4][4];
            #pragma unroll
            for (int am = 0; am < 4; am++) {
                const uint32_t addr = as +
                    (uint32_t)(((m0 + am * 16 + lrow) * GP + k0 + lcol) * 2);
                ldsm_x4(a[am][0], a[am][1], a[am][2], a[am][3], addr);
            }
            unsigned bf[8][2];
            #pragma unroll
            for (int j = 0; j < 4; j++) {
                const uint32_t addr = bs +
                    (uint32_t)(((n0 + j * 16 + lrow) * GP + k0 + lcol) * 2);
                unsigned r0, r1, r2, r3;
                ldsm_x4(r0, r1, r2, r3, addr);
                bf[2 * j][0] = r0; bf[2 * j + 1][0] = r1;
                bf[2 * j][1] = r2; bf[2 * j + 1][1] = r3;
            }
            #pragma unroll
            for (int am = 0; am < 4; am++)
                #pragma unroll
                for (int an = 0; an < 8; an++)
                    mma_f16(acc[am][an], a[am][0], a[am][1], a[am][2], a[am][3],
                            bf[an][0], bf[an][1]);
        }
        __syncthreads();
        if (it < 6) issue(it & 1, (it + 2) * 32);
    }

    #pragma unroll
    for (int am = 0; am < 4; am++) {
        #pragma unroll
        for (int an = 0; an < 8; an++) {
            const int col = colBase + n0 + an * 8 + 2 * tg;
            const float bi0 = bias[col], bi1 = bias[col + 1];
            #pragma unroll
            for (int half = 0; half < 2; half++) {
                const int row = rowBase + m0 + am * 16 + g + 8 * half;
                float2 v;
                v.x = acc[am][an][2 * half]     + bi0;
                v.y = acc[am][an][2 * half + 1] + bi1;
                if (QKV) {
                    const int b = row >> 6, n = row & 63;
                    const int which = col >> 8;
                    const int h = (col >> 5) & 7;
                    const int d = col & 31;
                    __half* dst = (which == 0) ? g_qh : (which == 1) ? g_kh : g_vh;
                    *(uint32_t*)&dst[((((size_t)b * HEADS + h) * WIN) + n) * HD + d] =
                        pack_f16(v.x, v.y);
                } else {
                    *(float2*)&out[(size_t)row * DIM + col] = v;
                }
            }
        }
    }
}

// ---------------------------------------------------------------------------
// Attention v5 + LDSM: QK plain fp16 (norms commuted), PV single fp16.
// ---------------------------------------------------------------------------
#define QP  40
#define PPB 72
#define VTP 72
#define ATTN_SMEM_BYTES 15360

__global__ void __launch_bounds__(128) attn_kernel(const float* __restrict__ logit_scale)
{
    extern __shared__ char smb[];
    __half* qs  = (__half*)(smb);
    __half* ks  = (__half*)(smb + 5120);
    __half* pm  = (__half*)(smb);            // alias (after QK reads)
    __half* vt  = (__half*)(smb + 10240);
    float* invq = (float*)(smb + 14848);
    float* invk = (float*)(smb + 15104);
    const uint32_t sqs = (uint32_t)__cvta_generic_to_shared(qs);
    const uint32_t sks = (uint32_t)__cvta_generic_to_shared(ks);
    const uint32_t spm = (uint32_t)__cvta_generic_to_shared(pm);
    const uint32_t svt = (uint32_t)__cvta_generic_to_shared(vt);

    const int bh = blockIdx.x;
    const int b  = bh >> 3;
    const int h  = bh & 7;
    const int tid  = threadIdx.x;
    const int lane = tid & 31;
    const int warp = tid >> 5;
    const int g  = lane >> 2, tg = lane & 3;
    const int m0 = warp * 16;
    const int r0 = m0 + g, r1 = r0 + 8;
    const int lrow = lane & 15;
    const int lcol = (lane >> 4) << 3;

    const size_t base = (size_t)bh * WIN * HD;
    const float ls = __expf(fminf(logit_scale[h], 4.6051701859880914f));

    // Phase 0: raw fp16 q/k copy + norms; v transpose
    {
        const int row = tid >> 1;
        const int d0  = (tid & 1) * 16;
        {
            uint32_t raw[8];
            const uint32_t* qp = (const uint32_t*)&g_qh[base + row * HD + d0];
            float s = 0.f;
            #pragma unroll
            for (int i = 0; i < 8; i++) {
                raw[i] = qp[i];
                float2 f = __half22float2(*(__half2*)&raw[i]);
                s += f.x * f.x + f.y * f.y;
            }
            s += __shfl_xor_sync(0xffffffffu, s, 1);
            if ((tid & 1) == 0) invq[row] = ls / fmaxf(sqrtf(s), 1e-12f);
            #pragma unroll
            for (int i = 0; i < 8; i++)
                *(uint32_t*)&qs[row * QP + d0 + 2 * i] = raw[i];
        }
        {
            uint32_t raw[8];
            const uint32_t* kp = (const uint32_t*)&g_kh[base + row * HD + d0];
            float s = 0.f;
            #pragma unroll
            for (int i = 0; i < 8; i++) {
                raw[i] = kp[i];
                float2 f = __half22float2(*(__half2*)&raw[i]);
                s += f.x * f.x + f.y * f.y;
            }
            s += __shfl_xor_sync(0xffffffffu, s, 1);
            if ((tid & 1) == 0) invk[row] = 1.0f / fmaxf(sqrtf(s), 1e-12f);
            #pragma unroll
            for (int i = 0; i < 8; i++)
                *(uint32_t*)&ks[row * QP + d0 + 2 * i] = raw[i];
        }
        #pragma unroll
        for (int i = 0; i < 4; i++) {
            const int idx = tid + 128 * i;
            const int n = idx >> 3, c = (idx & 7) * 4;
            const __half* vp = &g_vh[base + n * HD + c];
            __half2 v01 = *(const __half2*)(vp);
            __half2 v23 = *(const __half2*)(vp + 2);
            vt[(c + 0) * VTP + n] = __low2half(v01);
            vt[(c + 1) * VTP + n] = __high2half(v01);
            vt[(c + 2) * VTP + n] = __low2half(v23);
            vt[(c + 3) * VTP + n] = __high2half(v23);
        }
    }
    __syncthreads();

    // Prefetch bias+mask (fp16)
    float2 bm0[8], bm1[8];
    {
        const __half* bm = g_bmh + ((size_t)((b & 255) * 8 + h) << 12);
        #pragma unroll
        for (int an = 0; an < 8; an++) {
            const int c = an * 8 + 2 * tg;
            bm0[an] = __half22float2(*(const __half2*)&bm[r0 * 64 + c]);
            bm1[an] = __half22float2(*(const __half2*)&bm[r1 * 64 + c]);
        }
    }

    // QK^T: plain fp16 MMA, LDSM fragments
    float acc[8][4] = {};
    #pragma unroll
    for (int kst = 0; kst < 2; kst++) {
        const int kb = kst * 16;
        unsigned a0, a1, a2, a3;
        ldsm_x4(a0, a1, a2, a3,
                sqs + (uint32_t)(((m0 + lrow) * QP + kb + lcol) * 2));
        unsigned bf[8][2];
        #pragma unroll
        for (int j = 0; j < 4; j++) {
            unsigned r0v, r1v, r2v, r3v;
            ldsm_x4(r0v, r1v, r2v, r3v,
                    sks + (uint32_t)(((j * 16 + lrow) * QP + kb + lcol) * 2));
            bf[2 * j][0] = r0v; bf[2 * j + 1][0] = r1v;
            bf[2 * j][1] = r2v; bf[2 * j + 1][1] = r3v;
        }
        #pragma unroll
        for (int an = 0; an < 8; an++)
            mma_f16(acc[an], a0, a1, a2, a3, bf[an][0], bf[an][1]);
    }

    // Scale by norms + bias/mask
    const float iq0 = invq[r0], iq1 = invq[r1];
    #pragma unroll
    for (int an = 0; an < 8; an++) {
        const int c = an * 8 + 2 * tg;
        const float ik0 = invk[c], ik1 = invk[c + 1];
        acc[an][0] = acc[an][0] * iq0 * ik0 + bm0[an].x;
        acc[an][1] = acc[an][1] * iq0 * ik1 + bm0[an].y;
        acc[an][2] = acc[an][2] * iq1 * ik0 + bm1[an].x;
        acc[an][3] = acc[an][3] * iq1 * ik1 + bm1[an].y;
    }
    __syncthreads();   // all QK smem reads done before P writes alias q/k

    // Register softmax; write P fp16
    {
        float m0v = -1e30f, m1v = -1e30f;
        #pragma unroll
        for (int an = 0; an < 8; an++) {
            m0v = fmaxf(m0v, fmaxf(acc[an][0], acc[an][1]));
            m1v = fmaxf(m1v, fmaxf(acc[an][2], acc[an][3]));
        }
        m0v = fmaxf(m0v, __shfl_xor_sync(0xffffffffu, m0v, 1));
        m0v = fmaxf(m0v, __shfl_xor_sync(0xffffffffu, m0v, 2));
        m1v = fmaxf(m1v, __shfl_xor_sync(0xffffffffu, m1v, 1));
        m1v = fmaxf(m1v, __shfl_xor_sync(0xffffffffu, m1v, 2));
        float s0 = 0.f, s1 = 0.f;
        #pragma unroll
        for (int an = 0; an < 8; an++) {
            acc[an][0] = __expf(acc[an][0] - m0v); s0 += acc[an][0];
            acc[an][1] = __expf(acc[an][1] - m0v); s0 += acc[an][1];
            acc[an][2] = __expf(acc[an][2] - m1v); s1 += acc[an][2];
            acc[an][3] = __expf(acc[an][3] - m1v); s1 += acc[an][3];
        }
        s0 += __shfl_xor_sync(0xffffffffu, s0, 1);
        s0 += __shfl_xor_sync(0xffffffffu, s0, 2);
        s1 += __shfl_xor_sync(0xffffffffu, s1, 1);
        s1 += __shfl_xor_sync(0xffffffffu, s1, 2);
        const float i0 = 1.0f / s0, i1 = 1.0f / s1;
        #pragma unroll
        for (int an = 0; an < 8; an++) {
            const int c = an * 8 + 2 * tg;
            *(uint32_t*)&pm[r0 * PPB + c] = pack_f16(acc[an][0] * i0, acc[an][1] * i0);
            *(uint32_t*)&pm[r1 * PPB + c] = pack_f16(acc[an][2] * i1, acc[an][3] * i1);
        }
    }
    __syncwarp();

    // P @ V: single fp16 pass, LDSM fragments
    float oacc[4][4] = {};
    #pragma unroll
    for (int kst = 0; kst < 4; kst++) {
        const int kb = kst * 16;
        unsigned a0, a1, a2, a3;
        ldsm_x4(a0, a1, a2, a3,
                spm + (uint32_t)(((m0 + lrow) * PPB + kb + lcol) * 2));
        unsigned bf[4][2];
        #pragma unroll
        for (int j = 0; j < 2; j++) {
            unsigned r0v, r1v, r2v, r3v;
            ldsm_x4(r0v, r1v, r2v, r3v,
                    svt + (uint32_t)(((j * 16 + lrow) * VTP + kb + lcol) * 2));
            bf[2 * j][0] = r0v; bf[2 * j + 1][0] = r1v;
            bf[2 * j][1] = r2v; bf[2 * j + 1][1] = r3v;
        }
        #pragma unroll
        for (int dn = 0; dn < 4; dn++)
            mma_f16(oacc[dn], a0, a1, a2, a3, bf[dn][0], bf[dn][1]);
    }

    __half* aop = g_aoh + (size_t)b * WIN * DIM + h * HD;
    #pragma unroll
    for (int dn = 0; dn < 4; dn++) {
        const int c = dn * 8 + 2 * tg;
        *(uint32_t*)&aop[(size_t)r0 * DIM + c] = pack_f16(oacc[dn][0], oacc[dn][1]);
        *(uint32_t*)&aop[(size_t)r1 * DIM + c] = pack_f16(oacc[dn][2], oacc[dn][3]);
    }
}

// ---------------------------------------------------------------------------
extern "C" void kernel_launch(void* const* d_in, const int* in_sizes, int n_in,
                              void* d_out, int out_size)
{
    const float* x        = (const float*)d_in[0];
    const float* mask     = (const float*)d_in[1];
    const float* qkv_w    = (const float*)d_in[2];
    const float* qkv_b    = (const float*)d_in[3];
    const float* proj_w   = (const float*)d_in[4];
    const float* proj_b   = (const float*)d_in[5];
    const float* lscale   = (const float*)d_in[6];
    const float* btable   = (const float*)d_in[7];
    const int*   rpi      = (const int*)d_in[8];
    float* out = (float*)d_out;

    cudaFuncSetAttribute(attn_kernel, cudaFuncAttributeMaxDynamicSharedMemorySize,
                         ATTN_SMEM_BYTES);

    __half *xh, *wqh, *wph, *aoh;
    cudaGetSymbolAddress((void**)&xh,  g_xh);
    cudaGetSymbolAddress((void**)&wqh, g_wqh);
    cudaGetSymbolAddress((void**)&wph, g_wph);
    cudaGetSymbolAddress((void**)&aoh, g_aoh);

    // 0) pre-passes
    conv_f16<<<(MROWS*DIM/4 + 255)/256, 256>>>(x, xh, MROWS*DIM/4);
    conv_f16<<<(QKV_N*DIM/4 + 255)/256, 256>>>(qkv_w, wqh, QKV_N*DIM/4);
    conv_f16<<<(DIM*DIM/4 + 255)/256, 256>>>(proj_w, wph, DIM*DIM/4);
    bm_pre<<<8192, 256>>>(btable, rpi, mask);

    // 1) QKV projection
    {
        dim3 grid(QKV_N / 128, MROWS / 128);
        mma_gemm<true><<<grid, 128>>>(xh, wqh, qkv_b, nullptr);
    }
    // 2) Attention per (window, head)
    {
        attn_kernel<<<NWIN * HEADS, 128, ATTN_SMEM_BYTES>>>(lscale);
    }
    // 3) Output projection
    {
        dim3 grid(DIM / 128, MROWS / 128);
        mma_gemm<false><<<grid, 128>>>(aoh, wph, proj_b, out);
    }
}